// round 16
// baseline (speedup 1.0000x reference)
#include <cuda_runtime.h>
#include <cuda_fp16.h>
#include <math.h>
#include <stdint.h>

// Problem constants
#define BB   4
#define TT   2048
#define EMB  1024
#define NH   16
#define HD   64
#define MM   (BB * TT)          // 8192 rows

// ---------------------------------------------------------------------------
// Scratch (device globals; no allocation allowed)
// ---------------------------------------------------------------------------
__device__ __half g_ahi[MM * EMB];          // A hi (x, then attn out)
__device__ __half g_whi[4 * EMB * EMB];     // W^T [N][K] fp16, 4 weights
__device__ __half g_qhi[MM * EMB];          // Q [b,h,t,d] (pre-scaled)
__device__ __half g_khi[MM * EMB];          // K [b,h,t,d]
__device__ __half g_vthi[MM * EMB];         // V^T [b,h,d,t]

// ---------------------------------------------------------------------------
// Helpers (plain-sm_103-safe PTX: ldmatrix / mma.sync / cp.async)
// ---------------------------------------------------------------------------
__device__ __forceinline__ uint32_t smem_u32(const void* p) {
    uint32_t a;
    asm("{ .reg .u64 t; cvta.to.shared.u64 t, %1; cvt.u32.u64 %0, t; }"
        : "=r"(a) : "l"(p));
    return a;
}

__device__ __forceinline__ uint32_t h2ex2(uint32_t x) {
    uint32_t r;
    asm("ex2.approx.f16x2 %0, %1;" : "=r"(r) : "r"(x));
    return r;
}

#define LDSM_X4(R, addr) \
    asm volatile("ldmatrix.sync.aligned.m8n8.x4.shared.b16 {%0,%1,%2,%3}, [%4];" \
        : "=r"((R)[0]), "=r"((R)[1]), "=r"((R)[2]), "=r"((R)[3]) : "r"(addr))

#define MMA16816(C, A, B) \
    asm volatile("mma.sync.aligned.m16n8k16.row.col.f32.f16.f16.f32 " \
        "{%0,%1,%2,%3}, {%4,%5,%6,%7}, {%8,%9}, {%0,%1,%2,%3};" \
        : "+f"((C)[0]), "+f"((C)[1]), "+f"((C)[2]), "+f"((C)[3]) \
        : "r"((A)[0]), "r"((A)[1]), "r"((A)[2]), "r"((A)[3]), \
          "r"((B)[0]), "r"((B)[1]))

#define CP_ASYNC16(dst, src) \
    asm volatile("cp.async.cg.shared.global [%0], [%1], 16;" :: "r"(dst), "l"(src))
#define CP_COMMIT() asm volatile("cp.async.commit_group;")
#define CP_WAIT1()  asm volatile("cp.async.wait_group 1;")
#define CP_WAIT0()  asm volatile("cp.async.wait_group 0;")

__device__ __forceinline__ uint32_t pack2h(float x, float y) {
    __half2 h2 = __floats2half2_rn(x, y);
    return *(uint32_t*)&h2;
}

#define SCALE2 0.180336880f   // 0.125 * log2(e), folded into Q at projection

// ---------------------------------------------------------------------------
// convert_x: fp32 [8192,1024] -> fp16
// ---------------------------------------------------------------------------
__global__ __launch_bounds__(256)
void convert_x(const float* __restrict__ X, __half* __restrict__ hi)
{
    int idx = blockIdx.x * 256 + threadIdx.x;
    size_t e = (size_t)idx * 4;
    float4 v = *(const float4*)(X + e);
    uint2 hw;
    hw.x = pack2h(v.x, v.y);
    hw.y = pack2h(v.z, v.w);
    *(uint2*)(hi + e) = hw;
}

// ---------------------------------------------------------------------------
// split_wt4: 4 weights W [K,N] fp32 -> W^T [N,K] fp16 (fused, z = weight)
// ---------------------------------------------------------------------------
__global__ __launch_bounds__(256)
void split_wt4(const float* __restrict__ W0, const float* __restrict__ W1,
               const float* __restrict__ W2, const float* __restrict__ W3,
               __half* __restrict__ hi)
{
    __shared__ float ts[32][33];
    const int n0 = blockIdx.x * 32, k0 = blockIdx.y * 32;
    const int wz = blockIdx.z;
    const int tx = threadIdx.x, ty = threadIdx.y;
    const float* W = (wz == 0) ? W0 : (wz == 1) ? W1 : (wz == 2) ? W2 : W3;
    __half* dst = hi + (size_t)wz * EMB * EMB;

#pragma unroll
    for (int p = 0; p < 4; p++) {
        int ky = ty + p * 8;
        ts[ky][tx] = W[(size_t)(k0 + ky) * EMB + n0 + tx];
    }
    __syncthreads();
#pragma unroll
    for (int p = 0; p < 4; p++) {
        int ny = ty + p * 8;
        dst[(size_t)(n0 + ny) * EMB + k0 + tx] = __float2half(ts[tx][ny]);
    }
}

// ---------------------------------------------------------------------------
// Wide GEMM geometry: CTA 128x256, 512 threads (16 warps, 2x8), warp 64x32.
// Stage: A[128x64] + W[256x64], padded rows TP2=72. 2-stage pipeline.
// ---------------------------------------------------------------------------
#define TP2   72
#define GTSZ  (128 * TP2)            // A tile halves
#define GSMEMW (2 * 3 * GTSZ * 2)    // 110592 bytes (stage = 3*GTSZ halves)

// per-stage loader: 3072 16B-chunks over 512 threads (6 each)
#define WLOAD_STAGE(s, k0_)                                                   \
    do {                                                                      \
        _Pragma("unroll")                                                     \
        for (int p = 0; p < 6; p++) {                                         \
            int c = tid + p * 512;                                            \
            int isw = (c >= 1024);                                            \
            int row = isw ? ((c - 1024) >> 3) : (c >> 3);                     \
            int c8 = c & 7;                                                   \
            uint32_t off = (isw ? GTSZ : 0) + row * TP2;                      \
            uint32_t dst = sbase + ((s) * 3 * GTSZ + off + c8 * 8) * 2;       \
            const __half* sp = isw ? Wsrc : Asrc;                             \
            const void* src = sp + (size_t)row * EMB + (k0_) + c8 * 8;        \
            CP_ASYNC16(dst, src);                                             \
        }                                                                     \
        CP_COMMIT();                                                          \
    } while (0)

#define WGEMM_MAINLOOP                                                         \
    for (int kt = 0; kt < 16; kt++) {                                          \
        const int s = kt & 1;                                                  \
        if (kt < 15) { WLOAD_STAGE(s ^ 1, (kt + 1) * 64); CP_WAIT1(); }        \
        else         { CP_WAIT0(); }                                           \
        __syncthreads();                                                       \
        const uint32_t st = sbase + s * 3 * GTSZ * 2;                          \
        _Pragma("unroll")                                                      \
        for (int kc = 0; kc < 64; kc += 16) {                                  \
            uint32_t ah[4][4], bh[4][2];                                       \
            _Pragma("unroll")                                                  \
            for (int i = 0; i < 4; i++) {                                      \
                int row = wm * 64 + i * 16 + arow_in;                          \
                LDSM_X4(ah[i], st + (row * TP2 + kc + ak_half) * 2);           \
            }                                                                  \
            _Pragma("unroll")                                                  \
            for (int j = 0; j < 2; j++) {                                      \
                int nrow = wn * 32 + j * 16 + brow_in;                         \
                uint32_t addr = st + (GTSZ + nrow * TP2 + kc + bk_half) * 2;   \
                uint32_t r4[4];                                                \
                LDSM_X4(r4, addr);                                             \
                bh[2 * j][0] = r4[0]; bh[2 * j][1] = r4[1];                    \
                bh[2 * j + 1][0] = r4[2]; bh[2 * j + 1][1] = r4[3];            \
            }                                                                  \
            _Pragma("unroll")                                                  \
            for (int i = 0; i < 4; i++)                                        \
                _Pragma("unroll")                                              \
                for (int j = 0; j < 4; j++)                                    \
                    MMA16816(acc[i][j], ah[i], bh[j]);                         \
        }                                                                      \
        __syncthreads();                                                       \
    }

// ---------------------------------------------------------------------------
// gemm_qkv: fused QKV projection, 1-term, CTA 128x256.
// grid (12, 64): wi = blockIdx.x>>2 selects weight; (blockIdx.x&3)*256 = n base.
// Q output pre-scaled by SCALE2.
// ---------------------------------------------------------------------------
__global__ __launch_bounds__(512, 1)
void gemm_qkv(const __half* __restrict__ Ahi, const __half* __restrict__ Whb,
              const float* __restrict__ b0, const float* __restrict__ b1,
              const float* __restrict__ b2,
              __half* __restrict__ Qd, __half* __restrict__ Kd,
              __half* __restrict__ Vtd)
{
    extern __shared__ __align__(128) __half sm[];
    const uint32_t sbase = smem_u32(sm);
    const int tid  = threadIdx.x;
    const int lane = tid & 31;
    const int warp = tid >> 5;
    const int wm = warp >> 3;          // 0..1
    const int wn = warp & 7;           // 0..7
    const int wi = blockIdx.x >> 2;
    const int nb = (blockIdx.x & 3) * 256;
    const int m0 = blockIdx.y * 128;

    const __half* Asrc = Ahi + (size_t)m0 * EMB;
    const __half* Wsrc = Whb + (size_t)wi * EMB * EMB + (size_t)nb * EMB;
    const float* bias = (wi == 0) ? b0 : (wi == 1) ? b1 : b2;

    float acc[4][4][4] = {};

    WLOAD_STAGE(0, 0);

    const int arow_in = (lane & 7) + ((lane >> 3) & 1) * 8;
    const int ak_half = (lane >> 4) * 8;
    const int bg      = lane >> 3;
    const int brow_in = (lane & 7) + ((bg >> 1) & 1) * 8;
    const int bk_half = (bg & 1) * 8;

    WGEMM_MAINLOOP

    // ---- epilogue -> fp16 attention operands ----
    const int ln4 = lane >> 2;
    const int lm4 = lane & 3;
    const float qsc = (wi == 0) ? SCALE2 : 1.0f;
#pragma unroll
    for (int j = 0; j < 4; j++) {
        int nw = nb + wn * 32 + j * 8 + lm4 * 2;   // 0..1023 within weight
        float2 bj = *(const float2*)(bias + nw);
        int hh = nw >> 6;
        int d  = nw & 63;
#pragma unroll
        for (int i = 0; i < 4; i++) {
#pragma unroll
            for (int half = 0; half < 2; half++) {
                int m = m0 + wm * 64 + i * 16 + ln4 + half * 8;
                float rx = (acc[i][j][half * 2 + 0] + bj.x) * qsc;
                float ry = (acc[i][j][half * 2 + 1] + bj.y) * qsc;
                int b = m >> 11;
                int t = m & (TT - 1);
                if (wi < 2) {
                    __half* dst = (wi == 0) ? Qd : Kd;
                    size_t idx = (((size_t)(b * NH + hh) * TT + t) * HD) + d;
                    *(uint32_t*)(dst + idx) = pack2h(rx, ry);
                } else {
                    size_t idx = (((size_t)(b * NH + hh) * HD + d) * TT) + t;
                    Vtd[idx]      = __float2half(rx);
                    Vtd[idx + TT] = __float2half(ry);
                }
            }
        }
    }
}

// ---------------------------------------------------------------------------
// gemm_out: output projection, 1-term, CTA 128x256, fp32 out. grid (4, 64).
// ---------------------------------------------------------------------------
__global__ __launch_bounds__(512, 1)
void gemm_out(const __half* __restrict__ Ahi, const __half* __restrict__ Wh,
              const float* __restrict__ bias, float* __restrict__ C)
{
    extern __shared__ __align__(128) __half sm[];
    const uint32_t sbase = smem_u32(sm);
    const int tid  = threadIdx.x;
    const int lane = tid & 31;
    const int warp = tid >> 5;
    const int wm = warp >> 3;
    const int wn = warp & 7;
    const int n0 = blockIdx.x * 256;
    const int m0 = blockIdx.y * 128;

    const __half* Asrc = Ahi + (size_t)m0 * EMB;
    const __half* Wsrc = Wh + (size_t)n0 * EMB;

    float acc[4][4][4] = {};

    WLOAD_STAGE(0, 0);

    const int arow_in = (lane & 7) + ((lane >> 3) & 1) * 8;
    const int ak_half = (lane >> 4) * 8;
    const int bg      = lane >> 3;
    const int brow_in = (lane & 7) + ((bg >> 1) & 1) * 8;
    const int bk_half = (bg & 1) * 8;

    WGEMM_MAINLOOP

    const int ln4 = lane >> 2;
    const int lm4 = lane & 3;
#pragma unroll
    for (int j = 0; j < 4; j++) {
        int n = n0 + wn * 32 + j * 8 + lm4 * 2;
        float2 bj = *(const float2*)(bias + n);
#pragma unroll
        for (int i = 0; i < 4; i++) {
#pragma unroll
            for (int half = 0; half < 2; half++) {
                int m = m0 + wm * 64 + i * 16 + ln4 + half * 8;
                float2 res;
                res.x = acc[i][j][half * 2 + 0] + bj.x;
                res.y = acc[i][j][half * 2 + 1] + bj.y;
                *(float2*)(C + (size_t)m * EMB + n) = res;
            }
        }
    }
}

// ---------------------------------------------------------------------------
// Tensor-core causal flash attention (R14-validated no-max form, unchanged)
// ---------------------------------------------------------------------------
#define TPK   72
#define TPV   136
#define QTSZ  (128 * TPK)
#define KTSZ  (128 * TPK)
#define VTSZ  (64 * TPV)
#define STSZ  (KTSZ + VTSZ)
#define ASMEM ((QTSZ + 2 * STSZ) * 2)   // 90112 bytes

__global__ __launch_bounds__(256, 2)
void attn_tc(const __half* __restrict__ Qh, const __half* __restrict__ Kh,
             const __half* __restrict__ Vh, __half* __restrict__ Oh)
{
    extern __shared__ __align__(128) __half smb[];
    const uint32_t sb = smem_u32(smb);
    const int tid = threadIdx.x, lane = tid & 31, w = tid >> 5;
    const int qt = gridDim.x - 1 - blockIdx.x;
    const int h = blockIdx.y, b = blockIdx.z;
    const int bh = b * NH + h;
    const size_t kbase = (size_t)bh * TT * HD;
    const size_t vbase = (size_t)bh * HD * TT;
    const int nst = qt + 1;
    const int nch = 2 * nst;

    // ---- Q tile ----
    {
#pragma unroll
        for (int p = 0; p < 4; p++) {
            int c = tid + p * 256;
            int row = c >> 3, c8 = c & 7;
            uint32_t dst = sb + (row * TPK + c8 * 8) * 2;
            const __half* src = Qh + kbase + (size_t)(128 * qt + row) * HD + c8 * 8;
            CP_ASYNC16(dst, src);
        }
        CP_COMMIT();
    }

#define LOADST(s, st_)                                                          \
    do {                                                                        \
        _Pragma("unroll")                                                       \
        for (int p = 0; p < 8; p++) {                                           \
            int c = tid + p * 256;                                              \
            uint32_t dst;                                                       \
            const __half* src;                                                  \
            if (p < 4) {                                                        \
                int row = c >> 3, c8 = c & 7;                                   \
                dst = sb + (QTSZ + (s) * STSZ + row * TPK + c8 * 8) * 2;        \
                src = Kh + kbase + (size_t)(128 * (st_) + row) * HD + c8 * 8;   \
            } else {                                                            \
                int cc = c - 1024;                                              \
                int row = cc >> 4, c16 = cc & 15;                               \
                dst = sb + (QTSZ + (s) * STSZ + KTSZ + row * TPV + c16 * 8) * 2;\
                src = Vh + vbase + (size_t)row * TT + 128 * (st_) + c16 * 8;    \
            }                                                                   \
            CP_ASYNC16(dst, src);                                               \
        }                                                                       \
        CP_COMMIT();                                                            \
    } while (0)

    LOADST(0, 0);
    CP_WAIT1();
    __syncthreads();

    const int arow_in = (lane & 7) + ((lane >> 3) & 1) * 8;
    const int ak_half = (lane >> 4) * 8;
    const int bg      = lane >> 3;
    const int brow_in = (lane & 7) + ((bg >> 1) & 1) * 8;
    const int bk_half = (bg & 1) * 8;

    uint32_t qf[4][4];
#pragma unroll
    for (int kt = 0; kt < 4; kt++) {
        uint32_t qaddr = sb + ((16 * w + arow_in) * TPK + 16 * kt + ak_half) * 2;
        LDSM_X4(qf[kt], qaddr);
    }

    const int r0 = lane >> 2;
    const int c0 = 2 * (lane & 3);
    float l0s = 0.0f, l1s = 0.0f;
    float o[8][4] = {};

    for (int st = 0; st < nst; st++) {
        const int s = st & 1;
        if (st + 1 < nst) { LOADST(s ^ 1, st + 1); CP_WAIT1(); }
        else              { CP_WAIT0(); }
        __syncthreads();

        const uint32_t kstb = sb + (QTSZ + s * STSZ) * 2;
        const uint32_t vstb = kstb + KTSZ * 2;

#pragma unroll
        for (int sub = 0; sub < 2; sub++) {
            const int jc = 2 * st + sub;
            if (64 * jc > 128 * qt + 16 * w + 15) continue;

            // ---- S = Qh Kh^T ----
            float sa[8][4] = {};
#pragma unroll
            for (int kt = 0; kt < 4; kt++) {
#pragma unroll
                for (int jt = 0; jt < 4; jt++) {
                    uint32_t kh4[4];
                    uint32_t addr = kstb + ((64 * sub + 16 * jt + brow_in) * TPK
                                            + 16 * kt + bk_half) * 2;
                    LDSM_X4(kh4, addr);
                    MMA16816(sa[2 * jt],     qf[kt], kh4);
                    MMA16816(sa[2 * jt + 1], qf[kt], kh4 + 2);
                }
            }

            // ---- causal mask (diagonal chunks only) ----
            if (jc >= nch - 2) {
                int q0 = 128 * qt + 16 * w + r0;
                int k0 = 64 * jc;
#pragma unroll
                for (int j = 0; j < 8; j++) {
                    int key = k0 + 8 * j + c0;
                    if (key     > q0)     sa[j][0] = -1e30f;
                    if (key + 1 > q0)     sa[j][1] = -1e30f;
                    if (key     > q0 + 8) sa[j][2] = -1e30f;
                    if (key + 1 > q0 + 8) sa[j][3] = -1e30f;
                }
            }

            // ---- no-max softmax: p = ex2(s) in f16x2 ----
            uint32_t es[8][2];
#pragma unroll
            for (int j = 0; j < 8; j++) {
                __half2 hd0 = __floats2half2_rn(sa[j][0], sa[j][1]);
                __half2 hd1 = __floats2half2_rn(sa[j][2], sa[j][3]);
                es[j][0] = h2ex2(*(uint32_t*)&hd0);
                es[j][1] = h2ex2(*(uint32_t*)&hd1);
                float2 f0 = __half22float2(*(__half2*)&es[j][0]);
                float2 f1 = __half22float2(*(__half2*)&es[j][1]);
                l0s += f0.x + f0.y;
                l1s += f1.x + f1.y;
            }

            // ---- O += Ph V ----
#pragma unroll
            for (int kt = 0; kt < 4; kt++) {
                uint32_t ph4[4] = { es[2 * kt][0], es[2 * kt][1],
                                    es[2 * kt + 1][0], es[2 * kt + 1][1] };
#pragma unroll
                for (int jt = 0; jt < 4; jt++) {
                    uint32_t vh4[4];
                    uint32_t addr = vstb + ((16 * jt + brow_in) * TPV
                                            + 64 * sub + 16 * kt + bk_half) * 2;
                    LDSM_X4(vh4, addr);
                    MMA16816(o[2 * jt],     ph4, vh4);
                    MMA16816(o[2 * jt + 1], ph4, vh4 + 2);
                }
            }
        }
        __syncthreads();
    }

    // ---- epilogue ----
    l0s += __shfl_xor_sync(0xffffffffu, l0s, 1);
    l0s += __shfl_xor_sync(0xffffffffu, l0s, 2);
    l1s += __shfl_xor_sync(0xffffffffu, l1s, 1);
    l1s += __shfl_xor_sync(0xffffffffu, l1s, 2);
    float inv0 = 1.0f / l0s, inv1 = 1.0f / l1s;
    int t0 = 128 * qt + 16 * w + r0;
#pragma unroll
    for (int j = 0; j < 8; j++) {
        int e = h * 64 + 8 * j + c0;
        size_t idx0 = (size_t)(b * TT + t0) * EMB + e;
        *(uint32_t*)(Oh + idx0) = pack2h(o[j][0] * inv0, o[j][1] * inv0);
        size_t idx1 = (size_t)(b * TT + t0 + 8) * EMB + e;
        *(uint32_t*)(Oh + idx1) = pack2h(o[j][2] * inv1, o[j][3] * inv1);
    }
}

// ---------------------------------------------------------------------------
// Launch
// ---------------------------------------------------------------------------
extern "C" void kernel_launch(void* const* d_in, const int* in_sizes, int n_in,
                              void* d_out, int out_size)
{
    const float* x  = (const float*)d_in[0];
    const float* Wq = (const float*)d_in[1];
    const float* bq = (const float*)d_in[2];
    const float* Wk = (const float*)d_in[3];
    const float* bk = (const float*)d_in[4];
    const float* Wv = (const float*)d_in[5];
    const float* bv = (const float*)d_in[6];
    const float* Wo = (const float*)d_in[7];
    const float* bo = (const float*)d_in[8];
    float* out = (float*)d_out;

    __half *ahi, *whi, *qhi, *khi, *vthi;
    cudaGetSymbolAddress((void**)&ahi, g_ahi);
    cudaGetSymbolAddress((void**)&whi, g_whi);
    cudaGetSymbolAddress((void**)&qhi, g_qhi);
    cudaGetSymbolAddress((void**)&khi, g_khi);
    cudaGetSymbolAddress((void**)&vthi, g_vthi);

    cudaFuncSetAttribute(gemm_qkv, cudaFuncAttributeMaxDynamicSharedMemorySize, GSMEMW);
    cudaFuncSetAttribute(gemm_out, cudaFuncAttributeMaxDynamicSharedMemorySize, GSMEMW);
    cudaFuncSetAttribute(attn_tc, cudaFuncAttributeMaxDynamicSharedMemorySize, ASMEM);

    const size_t WS = (size_t)EMB * EMB;

    // Prep
    convert_x<<<(MM * EMB / 4) / 256, 256>>>(x, ahi);
    dim3 wt_grid(EMB / 32, EMB / 32, 4);
    dim3 wt_blk(32, 8);
    split_wt4<<<wt_grid, wt_blk>>>(Wq, Wk, Wv, Wo, whi);

    // Fused QKV projection (wide tiles)
    dim3 qkv_grid(12, MM / 128);        // (12, 64)
    gemm_qkv<<<qkv_grid, 512, GSMEMW>>>(ahi, whi, bq, bk, bv, qhi, khi, vthi);

    // Attention (writes ahi = A of final GEMM)
    dim3 attn_grid(TT / 128, NH, BB);   // (16, 16, 4)
    attn_tc<<<attn_grid, 256, ASMEM>>>(qhi, khi, vthi, ahi);

    // Output projection (wide tiles, fp32 out)
    dim3 ogrid(EMB / 256, MM / 128);    // (4, 64)
    gemm_out<<<ogrid, 512, GSMEMW>>>(ahi, whi + 3 * WS, bo, out);
}

// round 17
// speedup vs baseline: 1.0873x; 1.0873x over previous
#include <cuda_runtime.h>
#include <cuda_fp16.h>
#include <math.h>
#include <stdint.h>

// Problem constants
#define BB   4
#define TT   2048
#define EMB  1024
#define NH   16
#define HD   64
#define MM   (BB * TT)          // 8192 rows

// ---------------------------------------------------------------------------
// Scratch (device globals; no allocation allowed)
// ---------------------------------------------------------------------------
__device__ __half g_ahi[MM * EMB];          // A hi (x, then attn out)
__device__ __half g_whi[4 * EMB * EMB];     // W^T [N][K] fp16, 4 weights
__device__ __half g_qhi[MM * EMB];          // Q [b,h,t,d] (pre-scaled)
__device__ __half g_khi[MM * EMB];          // K [b,h,t,d]
__device__ __half g_vthi[MM * EMB];         // V^T [b,h,d,t]

// ---------------------------------------------------------------------------
// Helpers (plain-sm_103-safe PTX: ldmatrix / mma.sync / cp.async)
// ---------------------------------------------------------------------------
__device__ __forceinline__ uint32_t smem_u32(const void* p) {
    uint32_t a;
    asm("{ .reg .u64 t; cvta.to.shared.u64 t, %1; cvt.u32.u64 %0, t; }"
        : "=r"(a) : "l"(p));
    return a;
}

__device__ __forceinline__ uint32_t h2ex2(uint32_t x) {
    uint32_t r;
    asm("ex2.approx.f16x2 %0, %1;" : "=r"(r) : "r"(x));
    return r;
}

#define LDSM_X4(R, addr) \
    asm volatile("ldmatrix.sync.aligned.m8n8.x4.shared.b16 {%0,%1,%2,%3}, [%4];" \
        : "=r"((R)[0]), "=r"((R)[1]), "=r"((R)[2]), "=r"((R)[3]) : "r"(addr))

#define MMA16816(C, A, B) \
    asm volatile("mma.sync.aligned.m16n8k16.row.col.f32.f16.f16.f32 " \
        "{%0,%1,%2,%3}, {%4,%5,%6,%7}, {%8,%9}, {%0,%1,%2,%3};" \
        : "+f"((C)[0]), "+f"((C)[1]), "+f"((C)[2]), "+f"((C)[3]) \
        : "r"((A)[0]), "r"((A)[1]), "r"((A)[2]), "r"((A)[3]), \
          "r"((B)[0]), "r"((B)[1]))

#define CP_ASYNC16(dst, src) \
    asm volatile("cp.async.cg.shared.global [%0], [%1], 16;" :: "r"(dst), "l"(src))
#define CP_COMMIT() asm volatile("cp.async.commit_group;")
#define CP_WAIT2()  asm volatile("cp.async.wait_group 2;")
#define CP_WAIT1()  asm volatile("cp.async.wait_group 1;")
#define CP_WAIT0()  asm volatile("cp.async.wait_group 0;")

__device__ __forceinline__ uint32_t pack2h(float x, float y) {
    __half2 h2 = __floats2half2_rn(x, y);
    return *(uint32_t*)&h2;
}

#define SCALE2 0.180336880f   // 0.125 * log2(e), folded into Q at projection

// ---------------------------------------------------------------------------
// convert_x: fp32 [8192,1024] row-major -> fp16 row-major
// ---------------------------------------------------------------------------
__global__ __launch_bounds__(256)
void convert_x(const float* __restrict__ X, __half* __restrict__ hi)
{
    int idx = blockIdx.x * 256 + threadIdx.x;
    size_t e = (size_t)idx * 4;
    float4 v = *(const float4*)(X + e);
    uint2 hw;
    hw.x = pack2h(v.x, v.y);
    hw.y = pack2h(v.z, v.w);
    *(uint2*)(hi + e) = hw;
}

// ---------------------------------------------------------------------------
// split_wt4: 4 weights W [K,N] fp32 -> W^T [N,K] fp16 (fused, z = weight)
// ---------------------------------------------------------------------------
__global__ __launch_bounds__(256)
void split_wt4(const float* __restrict__ W0, const float* __restrict__ W1,
               const float* __restrict__ W2, const float* __restrict__ W3,
               __half* __restrict__ hi)
{
    __shared__ float ts[32][33];
    const int n0 = blockIdx.x * 32, k0 = blockIdx.y * 32;
    const int wz = blockIdx.z;
    const int tx = threadIdx.x, ty = threadIdx.y;
    const float* W = (wz == 0) ? W0 : (wz == 1) ? W1 : (wz == 2) ? W2 : W3;
    __half* dst = hi + (size_t)wz * EMB * EMB;

#pragma unroll
    for (int p = 0; p < 4; p++) {
        int ky = ty + p * 8;
        ts[ky][tx] = W[(size_t)(k0 + ky) * EMB + n0 + tx];
    }
    __syncthreads();
#pragma unroll
    for (int p = 0; p < 4; p++) {
        int ny = ty + p * 8;
        dst[(size_t)(n0 + ny) * EMB + k0 + tx] = __float2half(ts[tx][ny]);
    }
}

// ---------------------------------------------------------------------------
// Shared GEMM geometry (R14-validated: 1-term, 2 tiles/stage, 3-stage)
// ---------------------------------------------------------------------------
#define TP2   72
#define TSZ2  (128 * TP2)
#define GSMEM (3 * 2 * TSZ2 * 2)    // 110592 bytes

#define GLOAD_STAGE(s, k0_)                                                   \
    do {                                                                      \
        _Pragma("unroll")                                                     \
        for (int p = 0; p < 8; p++) {                                         \
            int c = tid + p * 256;                                            \
            int t = c >> 10;                                                  \
            int r = (c >> 3) & 127;                                           \
            int c8 = c & 7;                                                   \
            uint32_t dst = sbase + (((s) * 2 + t) * TSZ2 + r * TP2 + c8 * 8) * 2; \
            const void* src = srcs[t] + (size_t)r * EMB + (k0_) + c8 * 8;     \
            CP_ASYNC16(dst, src);                                             \
        }                                                                     \
        CP_COMMIT();                                                          \
    } while (0)

#define GEMM_MAINLOOP                                                          \
    for (int kt = 0; kt < 16; kt++) {                                          \
        const int s = kt % 3;                                                  \
        if (kt < 14)       { GLOAD_STAGE((kt + 2) % 3, (kt + 2) * 64); CP_WAIT2(); } \
        else if (kt == 14) { CP_WAIT1(); }                                     \
        else               { CP_WAIT0(); }                                     \
        __syncthreads();                                                       \
        const uint32_t st = sbase + s * 2 * TSZ2 * 2;                          \
        _Pragma("unroll")                                                      \
        for (int kc = 0; kc < 64; kc += 16) {                                  \
            uint32_t ah[4][4], bh[4][2];                                       \
            _Pragma("unroll")                                                  \
            for (int i = 0; i < 4; i++) {                                      \
                int row = wm * 64 + i * 16 + arow_in;                          \
                LDSM_X4(ah[i], st + (row * TP2 + kc + ak_half) * 2);           \
            }                                                                  \
            _Pragma("unroll")                                                  \
            for (int j = 0; j < 2; j++) {                                      \
                int nrow = wn * 32 + j * 16 + brow_in;                         \
                uint32_t addr = st + (TSZ2 + nrow * TP2 + kc + bk_half) * 2;   \
                uint32_t r4[4];                                                \
                LDSM_X4(r4, addr);                                             \
                bh[2 * j][0] = r4[0]; bh[2 * j][1] = r4[1];                    \
                bh[2 * j + 1][0] = r4[2]; bh[2 * j + 1][1] = r4[3];            \
            }                                                                  \
            _Pragma("unroll")                                                  \
            for (int i = 0; i < 4; i++)                                        \
                _Pragma("unroll")                                              \
                for (int j = 0; j < 4; j++)                                    \
                    MMA16816(acc[i][j], ah[i], bh[j]);                         \
        }                                                                      \
        __syncthreads();                                                       \
    }

// ---------------------------------------------------------------------------
// gemm_qkv: fused QKV projection, fp16 1-term (Ah@Wh).
// grid (24, 64): wi = blockIdx.x>>3 selects weight/bias/dst.
// Q output pre-scaled by SCALE2 (softmax exp2 domain).
// ---------------------------------------------------------------------------
__global__ __launch_bounds__(256, 2)
void gemm_qkv(const __half* __restrict__ Ahi, const __half* __restrict__ Whb,
              const float* __restrict__ b0, const float* __restrict__ b1,
              const float* __restrict__ b2,
              __half* __restrict__ Qd, __half* __restrict__ Kd,
              __half* __restrict__ Vtd)
{
    extern __shared__ __align__(128) __half sm[];
    const uint32_t sbase = smem_u32(sm);
    const int tid  = threadIdx.x;
    const int lane = tid & 31;
    const int warp = tid >> 5;
    const int wm = warp >> 2;
    const int wn = warp & 3;
    const int wi = blockIdx.x >> 3;
    const int n0 = (blockIdx.x & 7) * 128;
    const int m0 = blockIdx.y * 128;

    const __half* Wh = Whb + (size_t)wi * EMB * EMB;
    const float* bias = (wi == 0) ? b0 : (wi == 1) ? b1 : b2;

    const __half* srcs[2] = { Ahi + (size_t)m0 * EMB, Wh + (size_t)n0 * EMB };

    float acc[4][4][4] = {};

    GLOAD_STAGE(0, 0);
    GLOAD_STAGE(1, 64);

    const int arow_in = (lane & 7) + ((lane >> 3) & 1) * 8;
    const int ak_half = (lane >> 4) * 8;
    const int bg      = lane >> 3;
    const int brow_in = (lane & 7) + ((bg >> 1) & 1) * 8;
    const int bk_half = (bg & 1) * 8;

    GEMM_MAINLOOP

    // ---- epilogue -> fp16 attention operands ----
    const int ln4 = lane >> 2;
    const int lm4 = lane & 3;
    const float qsc = (wi == 0) ? SCALE2 : 1.0f;
#pragma unroll
    for (int j = 0; j < 4; j++) {
        int n = n0 + wn * 32 + j * 8 + lm4 * 2;
        float2 bj = *(const float2*)(bias + n);
        int hh = n >> 6;
        int d  = n & 63;
#pragma unroll
        for (int i = 0; i < 4; i++) {
#pragma unroll
            for (int half = 0; half < 2; half++) {
                int m = m0 + wm * 64 + i * 16 + ln4 + half * 8;
                float rx = (acc[i][j][half * 2 + 0] + bj.x) * qsc;
                float ry = (acc[i][j][half * 2 + 1] + bj.y) * qsc;
                int b = m >> 11;
                int t = m & (TT - 1);
                if (wi < 2) {
                    __half* dst = (wi == 0) ? Qd : Kd;
                    size_t idx = (((size_t)(b * NH + hh) * TT + t) * HD) + d;
                    *(uint32_t*)(dst + idx) = pack2h(rx, ry);
                } else {
                    size_t idx = (((size_t)(b * NH + hh) * HD + d) * TT) + t;
                    Vtd[idx]      = __float2half(rx);
                    Vtd[idx + TT] = __float2half(ry);
                }
            }
        }
    }
}

// ---------------------------------------------------------------------------
// gemm_out: output projection, fp16 1-term (Ah@Wh), fp32 out. grid (8, 64).
// ---------------------------------------------------------------------------
__global__ __launch_bounds__(256, 2)
void gemm_out(const __half* __restrict__ Ahi, const __half* __restrict__ Wh,
              const float* __restrict__ bias, float* __restrict__ C)
{
    extern __shared__ __align__(128) __half sm[];
    const uint32_t sbase = smem_u32(sm);
    const int tid  = threadIdx.x;
    const int lane = tid & 31;
    const int warp = tid >> 5;
    const int wm = warp >> 2;
    const int wn = warp & 3;
    const int n0 = blockIdx.x * 128;
    const int m0 = blockIdx.y * 128;

    const __half* srcs[2] = { Ahi + (size_t)m0 * EMB, Wh + (size_t)n0 * EMB };

    float acc[4][4][4] = {};

    GLOAD_STAGE(0, 0);
    GLOAD_STAGE(1, 64);

    const int arow_in = (lane & 7) + ((lane >> 3) & 1) * 8;
    const int ak_half = (lane >> 4) * 8;
    const int bg      = lane >> 3;
    const int brow_in = (lane & 7) + ((bg >> 1) & 1) * 8;
    const int bk_half = (bg & 1) * 8;

    GEMM_MAINLOOP

    const int ln4 = lane >> 2;
    const int lm4 = lane & 3;
#pragma unroll
    for (int j = 0; j < 4; j++) {
        int n = n0 + wn * 32 + j * 8 + lm4 * 2;
        float2 bj = *(const float2*)(bias + n);
#pragma unroll
        for (int i = 0; i < 4; i++) {
#pragma unroll
            for (int half = 0; half < 2; half++) {
                int m = m0 + wm * 64 + i * 16 + ln4 + half * 8;
                float2 res;
                res.x = acc[i][j][half * 2 + 0] + bj.x;
                res.y = acc[i][j][half * 2 + 1] + bj.y;
                *(float2*)(C + (size_t)m * EMB + n) = res;
            }
        }
    }
}

// ---------------------------------------------------------------------------
// Tensor-core causal flash attention, fp16, no-max softmax (R14 form),
// with l accumulated via fp16 HADD2 tree (saves ~42 scalar ops/chunk/thread).
// ---------------------------------------------------------------------------
#define TPK   72
#define TPV   136
#define QTSZ  (128 * TPK)
#define KTSZ  (128 * TPK)
#define VTSZ  (64 * TPV)
#define STSZ  (KTSZ + VTSZ)
#define ASMEM ((QTSZ + 2 * STSZ) * 2)   // 90112 bytes

__global__ __launch_bounds__(256, 2)
void attn_tc(const __half* __restrict__ Qh, const __half* __restrict__ Kh,
             const __half* __restrict__ Vh, __half* __restrict__ Oh)
{
    extern __shared__ __align__(128) __half smb[];
    const uint32_t sb = smem_u32(smb);
    const int tid = threadIdx.x, lane = tid & 31, w = tid >> 5;
    const int qt = gridDim.x - 1 - blockIdx.x;
    const int h = blockIdx.y, b = blockIdx.z;
    const int bh = b * NH + h;
    const size_t kbase = (size_t)bh * TT * HD;
    const size_t vbase = (size_t)bh * HD * TT;
    const int nst = qt + 1;
    const int nch = 2 * nst;

    // ---- Q tile ----
    {
#pragma unroll
        for (int p = 0; p < 4; p++) {
            int c = tid + p * 256;
            int row = c >> 3, c8 = c & 7;
            uint32_t dst = sb + (row * TPK + c8 * 8) * 2;
            const __half* src = Qh + kbase + (size_t)(128 * qt + row) * HD + c8 * 8;
            CP_ASYNC16(dst, src);
        }
        CP_COMMIT();
    }

#define LOADST(s, st_)                                                          \
    do {                                                                        \
        _Pragma("unroll")                                                       \
        for (int p = 0; p < 8; p++) {                                           \
            int c = tid + p * 256;                                              \
            uint32_t dst;                                                       \
            const __half* src;                                                  \
            if (p < 4) {                                                        \
                int row = c >> 3, c8 = c & 7;                                   \
                dst = sb + (QTSZ + (s) * STSZ + row * TPK + c8 * 8) * 2;        \
                src = Kh + kbase + (size_t)(128 * (st_) + row) * HD + c8 * 8;   \
            } else {                                                            \
                int cc = c - 1024;                                              \
                int row = cc >> 4, c16 = cc & 15;                               \
                dst = sb + (QTSZ + (s) * STSZ + KTSZ + row * TPV + c16 * 8) * 2;\
                src = Vh + vbase + (size_t)row * TT + 128 * (st_) + c16 * 8;    \
            }                                                                   \
            CP_ASYNC16(dst, src);                                               \
        }                                                                       \
        CP_COMMIT();                                                            \
    } while (0)

    LOADST(0, 0);
    CP_WAIT1();
    __syncthreads();

    const int arow_in = (lane & 7) + ((lane >> 3) & 1) * 8;
    const int ak_half = (lane >> 4) * 8;
    const int bg      = lane >> 3;
    const int brow_in = (lane & 7) + ((bg >> 1) & 1) * 8;
    const int bk_half = (bg & 1) * 8;

    uint32_t qf[4][4];
#pragma unroll
    for (int kt = 0; kt < 4; kt++) {
        uint32_t qaddr = sb + ((16 * w + arow_in) * TPK + 16 * kt + ak_half) * 2;
        LDSM_X4(qf[kt], qaddr);
    }

    const int r0 = lane >> 2;
    const int c0 = 2 * (lane & 3);
    float l0s = 0.0f, l1s = 0.0f;
    float o[8][4] = {};

    for (int st = 0; st < nst; st++) {
        const int s = st & 1;
        if (st + 1 < nst) { LOADST(s ^ 1, st + 1); CP_WAIT1(); }
        else              { CP_WAIT0(); }
        __syncthreads();

        const uint32_t kstb = sb + (QTSZ + s * STSZ) * 2;
        const uint32_t vstb = kstb + KTSZ * 2;

#pragma unroll
        for (int sub = 0; sub < 2; sub++) {
            const int jc = 2 * st + sub;
            if (64 * jc > 128 * qt + 16 * w + 15) continue;

            // ---- S = Qh Kh^T (already exp2-domain-scaled via Q) ----
            float sa[8][4] = {};
#pragma unroll
            for (int kt = 0; kt < 4; kt++) {
#pragma unroll
                for (int jt = 0; jt < 4; jt++) {
                    uint32_t kh4[4];
                    uint32_t addr = kstb + ((64 * sub + 16 * jt + brow_in) * TPK
                                            + 16 * kt + bk_half) * 2;
                    LDSM_X4(kh4, addr);
                    MMA16816(sa[2 * jt],     qf[kt], kh4);
                    MMA16816(sa[2 * jt + 1], qf[kt], kh4 + 2);
                }
            }

            // ---- causal mask (diagonal chunks only) ----
            if (jc >= nch - 2) {
                int q0 = 128 * qt + 16 * w + r0;
                int k0 = 64 * jc;
#pragma unroll
                for (int j = 0; j < 8; j++) {
                    int key = k0 + 8 * j + c0;
                    if (key     > q0)     sa[j][0] = -1e30f;
                    if (key + 1 > q0)     sa[j][1] = -1e30f;
                    if (key     > q0 + 8) sa[j][2] = -1e30f;
                    if (key + 1 > q0 + 8) sa[j][3] = -1e30f;
                }
            }

            // ---- no-max softmax: p = ex2(s) in f16x2 ----
            uint32_t es[8][2];
#pragma unroll
            for (int j = 0; j < 8; j++) {
                __half2 hd0 = __floats2half2_rn(sa[j][0], sa[j][1]);
                __half2 hd1 = __floats2half2_rn(sa[j][2], sa[j][3]);
                es[j][0] = h2ex2(*(uint32_t*)&hd0);
                es[j][1] = h2ex2(*(uint32_t*)&hd1);
            }

            // ---- l partial sums via fp16 HADD2 tree (3 levels) ----
            {
#define EH2(j, k) (*(__half2*)&es[j][k])
                __half2 a0 = __hadd2(__hadd2(EH2(0,0), EH2(1,0)),
                                     __hadd2(EH2(2,0), EH2(3,0)));
                __half2 a1 = __hadd2(__hadd2(EH2(4,0), EH2(5,0)),
                                     __hadd2(EH2(6,0), EH2(7,0)));
                __half2 b0 = __hadd2(__hadd2(EH2(0,1), EH2(1,1)),
                                     __hadd2(EH2(2,1), EH2(3,1)));
                __half2 b1 = __hadd2(__hadd2(EH2(4,1), EH2(5,1)),
                                     __hadd2(EH2(6,1), EH2(7,1)));
                float2 fa = __half22float2(__hadd2(a0, a1));
                float2 fb = __half22float2(__hadd2(b0, b1));
                l0s += fa.x + fa.y;
                l1s += fb.x + fb.y;
#undef EH2
            }

            // ---- O += Ph V ----
#pragma unroll
            for (int kt = 0; kt < 4; kt++) {
                uint32_t ph4[4] = { es[2 * kt][0], es[2 * kt][1],
                                    es[2 * kt + 1][0], es[2 * kt + 1][1] };
#pragma unroll
                for (int jt = 0; jt < 4; jt++) {
                    uint32_t vh4[4];
                    uint32_t addr = vstb + ((16 * jt + brow_in) * TPV
                                            + 64 * sub + 16 * kt + bk_half) * 2;
                    LDSM_X4(vh4, addr);
                    MMA16816(o[2 * jt],     ph4, vh4);
                    MMA16816(o[2 * jt + 1], ph4, vh4 + 2);
                }
            }
        }
        __syncthreads();
    }

    // ---- epilogue: quad reduction of l, normalize, store fp16 ----
    l0s += __shfl_xor_sync(0xffffffffu, l0s, 1);
    l0s += __shfl_xor_sync(0xffffffffu, l0s, 2);
    l1s += __shfl_xor_sync(0xffffffffu, l1s, 1);
    l1s += __shfl_xor_sync(0xffffffffu, l1s, 2);
    float inv0 = 1.0f / l0s, inv1 = 1.0f / l1s;
    int t0 = 128 * qt + 16 * w + r0;
#pragma unroll
    for (int j = 0; j < 8; j++) {
        int e = h * 64 + 8 * j + c0;
        size_t idx0 = (size_t)(b * TT + t0) * EMB + e;
        *(uint32_t*)(Oh + idx0) = pack2h(o[j][0] * inv0, o[j][1] * inv0);
        size_t idx1 = (size_t)(b * TT + t0 + 8) * EMB + e;
        *(uint32_t*)(Oh + idx1) = pack2h(o[j][2] * inv1, o[j][3] * inv1);
    }
}

// ---------------------------------------------------------------------------
// Launch
// ---------------------------------------------------------------------------
extern "C" void kernel_launch(void* const* d_in, const int* in_sizes, int n_in,
                              void* d_out, int out_size)
{
    const float* x  = (const float*)d_in[0];
    const float* Wq = (const float*)d_in[1];
    const float* bq = (const float*)d_in[2];
    const float* Wk = (const float*)d_in[3];
    const float* bk = (const float*)d_in[4];
    const float* Wv = (const float*)d_in[5];
    const float* bv = (const float*)d_in[6];
    const float* Wo = (const float*)d_in[7];
    const float* bo = (const float*)d_in[8];
    float* out = (float*)d_out;

    __half *ahi, *whi, *qhi, *khi, *vthi;
    cudaGetSymbolAddress((void**)&ahi, g_ahi);
    cudaGetSymbolAddress((void**)&whi, g_whi);
    cudaGetSymbolAddress((void**)&qhi, g_qhi);
    cudaGetSymbolAddress((void**)&khi, g_khi);
    cudaGetSymbolAddress((void**)&vthi, g_vthi);

    cudaFuncSetAttribute(gemm_qkv, cudaFuncAttributeMaxDynamicSharedMemorySize, GSMEM);
    cudaFuncSetAttribute(gemm_out, cudaFuncAttributeMaxDynamicSharedMemorySize, GSMEM);
    cudaFuncSetAttribute(attn_tc, cudaFuncAttributeMaxDynamicSharedMemorySize, ASMEM);

    const size_t WS = (size_t)EMB * EMB;

    // Prep
    convert_x<<<(MM * EMB / 4) / 256, 256>>>(x, ahi);
    dim3 wt_grid(EMB / 32, EMB / 32, 4);
    dim3 wt_blk(32, 8);
    split_wt4<<<wt_grid, wt_blk>>>(Wq, Wk, Wv, Wo, whi);

    // Fused QKV projection (1-term; Q pre-scaled)
    dim3 qkv_grid(24, MM / 128);        // (24, 64)
    gemm_qkv<<<qkv_grid, 256, GSMEM>>>(ahi, whi, bq, bk, bv, qhi, khi, vthi);

    // Attention (writes ahi = A of final GEMM)
    dim3 attn_grid(TT / 128, NH, BB);   // (16, 16, 4)
    attn_tc<<<attn_grid, 256, ASMEM>>>(qhi, khi, vthi, ahi);

    // Output projection (1-term, fp32 out)
    dim3 ogrid(EMB / 128, MM / 128);    // (8, 64)
    gemm_out<<<ogrid, 256, GSMEM>>>(ahi, whi + 3 * WS, bo, out);
}